// round 4
// baseline (speedup 1.0000x reference)
#include <cuda_runtime.h>
#include <math.h>

#define N_NODES 20000
#define N_EDGES 80000
#define DIM 64
#define EDIM 12
#define PCOLS 1024      // 12*64 W blocks | 64 bias | 192 gh = x @ w_hh^T
#define BN_EPS 1e-5f
#define BN_BLOCKS 160

// ---------------- scratch ----------------
__device__ float g_P[(size_t)N_NODES * PCOLS];     // 81.9 MB
__device__ float g_agg[(size_t)N_NODES * DIM];
__device__ float g_cnt[N_NODES];
__device__ float g_bnpart[BN_BLOCKS * 2 * EDIM];   // per-block partial sums / sumsq
__device__ float g_scale[EDIM];
__device__ float g_shift[EDIM];

__device__ __forceinline__ float f2tf32(float f) {
    unsigned u;
    asm("cvt.rna.tf32.f32 %0, %1;" : "=r"(u) : "f"(f));
    return __uint_as_float(u);
}

// ---------------- kernel 1: zero agg/cnt + BN partial sums ----------------
__global__ void k_bn_reduce(const float* __restrict__ ea) {
    int idx = blockIdx.x * blockDim.x + threadIdx.x;
    int stride = gridDim.x * blockDim.x;

    // zero scatter targets (float4 for agg)
    float4* aggz = (float4*)g_agg;
    for (int j = idx; j < N_NODES * DIM / 4; j += stride)
        aggz[j] = make_float4(0.f, 0.f, 0.f, 0.f);
    for (int j = idx; j < N_NODES; j += stride) g_cnt[j] = 0.f;

    // BN column sums (thread-local, then block partial)
    float s[EDIM], q[EDIM];
#pragma unroll
    for (int c = 0; c < EDIM; c++) { s[c] = 0.f; q[c] = 0.f; }
    for (int e = idx; e < N_EDGES; e += stride) {
        const float* row = ea + (size_t)e * EDIM;
#pragma unroll
        for (int c = 0; c < EDIM; c++) { float v = row[c]; s[c] += v; q[c] += v * v; }
    }
#pragma unroll
    for (int off = 16; off > 0; off >>= 1) {
#pragma unroll
        for (int c = 0; c < EDIM; c++) {
            s[c] += __shfl_down_sync(0xffffffffu, s[c], off);
            q[c] += __shfl_down_sync(0xffffffffu, q[c], off);
        }
    }
    __shared__ float bs[2 * EDIM];
    if (threadIdx.x < 2 * EDIM) bs[threadIdx.x] = 0.f;
    __syncthreads();
    if ((threadIdx.x & 31) == 0) {
#pragma unroll
        for (int c = 0; c < EDIM; c++) {
            atomicAdd(&bs[c], s[c]);
            atomicAdd(&bs[EDIM + c], q[c]);
        }
    }
    __syncthreads();
    if (threadIdx.x < 2 * EDIM)
        g_bnpart[blockIdx.x * 2 * EDIM + threadIdx.x] = bs[threadIdx.x];
}

// ---------------- kernel 2: BN finalize from partials ----------------
__global__ void k_bn_fin(const float* __restrict__ gamma, const float* __restrict__ beta) {
    int t = threadIdx.x;
    if (t < 2 * EDIM) {
        float acc = 0.f;
        for (int b = 0; b < BN_BLOCKS; b++) acc += g_bnpart[b * 2 * EDIM + t];
        __shared__ float red[2 * EDIM];
        red[t] = acc;
        __syncwarp();
        if (t < EDIM) {
            float inv_n = 1.0f / (float)N_EDGES;
            float mu = red[t] * inv_n;
            float var = red[EDIM + t] * inv_n - mu * mu;
            float sc = rsqrtf(var + BN_EPS) * gamma[t];
            g_scale[t] = sc;
            g_shift[t] = beta[t] - mu * sc;
        }
    }
}

// ---------------- mma helper ----------------
__device__ __forceinline__ void mma_tf32(float* c, const unsigned* a, unsigned b0, unsigned b1) {
    asm volatile(
        "mma.sync.aligned.m16n8k8.row.col.f32.tf32.tf32.f32 "
        "{%0,%1,%2,%3}, {%4,%5,%6,%7}, {%8,%9}, {%0,%1,%2,%3};"
        : "+f"(c[0]), "+f"(c[1]), "+f"(c[2]), "+f"(c[3])
        : "r"(a[0]), "r"(a[1]), "r"(a[2]), "r"(a[3]), "r"(b0), "r"(b1));
}

// ---------------- kernel 3: GEMM1  P = [X] @ B, B packed inline ----------------
// B[i][j]:  j<768: lin_w[j>>6, i*64 + (j&63)]
//           768<=j<832: lin_b[i*64 + j-768]
//           832<=j<1024: w_hh[j-832, i]   (transpose gather; L2-resident)
#define GA_PITCH 68
#define GB_PITCH 132
#define G1_SMEM ((128 * GA_PITCH + 64 * GB_PITCH) * 4)

__global__ void k_gemm1(const float* __restrict__ x, const float* __restrict__ lw,
                        const float* __restrict__ lb, const float* __restrict__ whh) {
    extern __shared__ float sm[];
    float* As = sm;                    // [128][68]
    float* Bs = sm + 128 * GA_PITCH;   // [64][132] k-major

    int tid = threadIdx.x;
    int m0 = blockIdx.x * 128;
    int n0 = blockIdx.y * 128;

    // A tile (128 x 64)
#pragma unroll
    for (int r = 0; r < 8; r++) {
        int id = r * 256 + tid;
        int m = id >> 4;
        int k4 = (id & 15) << 2;
        float4 v = make_float4(0.f, 0.f, 0.f, 0.f);
        if (m0 + m < N_NODES) v = *(const float4*)&x[(size_t)(m0 + m) * 64 + k4];
        v.x = f2tf32(v.x); v.y = f2tf32(v.y); v.z = f2tf32(v.z); v.w = f2tf32(v.w);
        *(float4*)&As[m * GA_PITCH + k4] = v;
    }
    // B tile (64 x 128) packed from inputs
#pragma unroll
    for (int r = 0; r < 8; r++) {
        int id = r * 256 + tid;
        int k = id >> 5;
        int n4 = (id & 31) << 2;
        int j0 = n0 + n4;
        float4 v;
        if (j0 < 768) {
            int kk = j0 >> 6, o = j0 & 63;
            v = *(const float4*)&lw[(size_t)kk * 4096 + k * 64 + o];
        } else if (j0 < 832) {
            v = *(const float4*)&lb[k * 64 + (j0 - 768)];
        } else {
            v.x = whh[(j0 - 832 + 0) * 64 + k];
            v.y = whh[(j0 - 832 + 1) * 64 + k];
            v.z = whh[(j0 - 832 + 2) * 64 + k];
            v.w = whh[(j0 - 832 + 3) * 64 + k];
        }
        v.x = f2tf32(v.x); v.y = f2tf32(v.y); v.z = f2tf32(v.z); v.w = f2tf32(v.w);
        *(float4*)&Bs[k * GB_PITCH + n4] = v;
    }
    __syncthreads();

    int wid = tid >> 5;
    int lane = tid & 31;
    int gid = lane >> 2;
    int tig = lane & 3;
    int warp_m = wid & 3;
    int warp_n = wid >> 2;

    float acc[2][8][4];
#pragma unroll
    for (int mt = 0; mt < 2; mt++)
#pragma unroll
        for (int nt = 0; nt < 8; nt++)
#pragma unroll
            for (int j = 0; j < 4; j++) acc[mt][nt][j] = 0.f;

#pragma unroll
    for (int ks = 0; ks < 8; ks++) {
        int k0 = ks * 8;
        unsigned a[2][4];
#pragma unroll
        for (int mt = 0; mt < 2; mt++) {
            int rowb = warp_m * 32 + mt * 16;
            a[mt][0] = __float_as_uint(As[(rowb + gid) * GA_PITCH + k0 + tig]);
            a[mt][1] = __float_as_uint(As[(rowb + gid + 8) * GA_PITCH + k0 + tig]);
            a[mt][2] = __float_as_uint(As[(rowb + gid) * GA_PITCH + k0 + tig + 4]);
            a[mt][3] = __float_as_uint(As[(rowb + gid + 8) * GA_PITCH + k0 + tig + 4]);
        }
#pragma unroll
        for (int nt = 0; nt < 8; nt++) {
            int nb = warp_n * 64 + nt * 8 + gid;
            unsigned b0 = __float_as_uint(Bs[(k0 + tig) * GB_PITCH + nb]);
            unsigned b1 = __float_as_uint(Bs[(k0 + tig + 4) * GB_PITCH + nb]);
            mma_tf32(acc[0][nt], a[0], b0, b1);
            mma_tf32(acc[1][nt], a[1], b0, b1);
        }
    }

#pragma unroll
    for (int mt = 0; mt < 2; mt++) {
#pragma unroll
        for (int nt = 0; nt < 8; nt++) {
            int col = n0 + warp_n * 64 + nt * 8 + tig * 2;
            int r0 = m0 + warp_m * 32 + mt * 16 + gid;
            if (r0 < N_NODES)
                *(float2*)&g_P[(size_t)r0 * PCOLS + col] = make_float2(acc[mt][nt][0], acc[mt][nt][1]);
            int r1 = r0 + 8;
            if (r1 < N_NODES)
                *(float2*)&g_P[(size_t)r1 * PCOLS + col] = make_float2(acc[mt][nt][2], acc[mt][nt][3]);
        }
    }
}

// ---------------- kernel 4: per-edge message + scatter (float2 lanes) ----------------
__global__ void k_edge(const float* __restrict__ ea, const int* __restrict__ ei) {
    int wg = (blockIdx.x * blockDim.x + threadIdx.x) >> 5;
    int lane = threadIdx.x & 31;
    if (wg >= N_EDGES) return;
    int e = wg;
    int src = ei[e];
    int dst = ei[N_EDGES + e];

    float eb = 0.f;
    if (lane < EDIM) eb = ea[(size_t)e * EDIM + lane] * g_scale[lane] + g_shift[lane];

    const float2* p2 = (const float2*)(g_P + (size_t)src * PCOLS);
    float2 acc = p2[384 + lane];  // bias block at col 768
#pragma unroll
    for (int k = 0; k < EDIM; k++) {
        float c = __shfl_sync(0xffffffffu, eb, k);
        float2 w = p2[k * 32 + lane];
        acc.x += c * w.x;
        acc.y += c * w.y;
    }
    float* a = g_agg + (size_t)dst * DIM + 2 * lane;
    atomicAdd(a, acc.x);
    atomicAdd(a + 1, acc.y);
    if (lane == 0) atomicAdd(&g_cnt[dst], 1.0f);
}

// ---------------- kernel 5: fused GI GEMM + GRU ----------------
// A = relu(agg)/cnt [128 x 64], B = w_ih^T [64 x 192]; epilogue does the GRU.
#define G2B_PITCH 196
#define G2_SMEM_FLOATS (128 * G2B_PITCH)   // 25088 floats; > As+Bs (8704+12544)
#define G2_SMEM (G2_SMEM_FLOATS * 4)

__global__ void k_gemm2_gru(const float* __restrict__ x, const float* __restrict__ wih,
                            const float* __restrict__ bih, const float* __restrict__ bhh,
                            float* __restrict__ out) {
    extern __shared__ float sm[];
    float* As = sm;                    // [128][68]
    float* Bs = sm + 128 * GA_PITCH;   // [64][196] k-major (cols 0..191)
    float* S  = sm;                    // staging [128][196] (reused after mainloop)
    __shared__ float sbih[192], sbhh[192];

    int tid = threadIdx.x;
    int m0 = blockIdx.x * 128;

    if (tid < 192) { sbih[tid] = bih[tid]; sbhh[tid] = bhh[tid]; }

    // A tile: relu(agg)/cnt, tf32
#pragma unroll
    for (int r = 0; r < 8; r++) {
        int id = r * 256 + tid;
        int m = id >> 4;
        int k4 = (id & 15) << 2;
        float4 v = make_float4(0.f, 0.f, 0.f, 0.f);
        int node = m0 + m;
        if (node < N_NODES) {
            float inv = 1.0f / fmaxf(g_cnt[node], 1.0f);
            float4 a = *(const float4*)&g_agg[(size_t)node * 64 + k4];
            v.x = fmaxf(a.x, 0.f) * inv;
            v.y = fmaxf(a.y, 0.f) * inv;
            v.z = fmaxf(a.z, 0.f) * inv;
            v.w = fmaxf(a.w, 0.f) * inv;
        }
        v.x = f2tf32(v.x); v.y = f2tf32(v.y); v.z = f2tf32(v.z); v.w = f2tf32(v.w);
        *(float4*)&As[m * GA_PITCH + k4] = v;
    }
    // B tile: wih^T via coalesced transpose load (192 g x 16 k4-slots = 3072)
#pragma unroll
    for (int r = 0; r < 12; r++) {
        int id = r * 256 + tid;
        int g = id >> 4;
        int k4 = (id & 15) << 2;
        float4 w = *(const float4*)&wih[(size_t)g * 64 + k4];
        Bs[(k4 + 0) * G2B_PITCH + g] = f2tf32(w.x);
        Bs[(k4 + 1) * G2B_PITCH + g] = f2tf32(w.y);
        Bs[(k4 + 2) * G2B_PITCH + g] = f2tf32(w.z);
        Bs[(k4 + 3) * G2B_PITCH + g] = f2tf32(w.w);
    }
    __syncthreads();

    int wid = tid >> 5;
    int lane = tid & 31;
    int gid = lane >> 2;
    int tig = lane & 3;
    int warp_m = wid & 3;      // 32 rows each
    int warp_n = wid >> 2;     // 96 cols each

    float acc[2][12][4];
#pragma unroll
    for (int mt = 0; mt < 2; mt++)
#pragma unroll
        for (int nt = 0; nt < 12; nt++)
#pragma unroll
            for (int j = 0; j < 4; j++) acc[mt][nt][j] = 0.f;

#pragma unroll
    for (int ks = 0; ks < 8; ks++) {
        int k0 = ks * 8;
        unsigned a[2][4];
#pragma unroll
        for (int mt = 0; mt < 2; mt++) {
            int rowb = warp_m * 32 + mt * 16;
            a[mt][0] = __float_as_uint(As[(rowb + gid) * GA_PITCH + k0 + tig]);
            a[mt][1] = __float_as_uint(As[(rowb + gid + 8) * GA_PITCH + k0 + tig]);
            a[mt][2] = __float_as_uint(As[(rowb + gid) * GA_PITCH + k0 + tig + 4]);
            a[mt][3] = __float_as_uint(As[(rowb + gid + 8) * GA_PITCH + k0 + tig + 4]);
        }
#pragma unroll
        for (int nt = 0; nt < 12; nt++) {
            int nb = warp_n * 96 + nt * 8 + gid;
            unsigned b0 = __float_as_uint(Bs[(k0 + tig) * G2B_PITCH + nb]);
            unsigned b1 = __float_as_uint(Bs[(k0 + tig + 4) * G2B_PITCH + nb]);
            mma_tf32(acc[0][nt], a[0], b0, b1);
            mma_tf32(acc[1][nt], a[1], b0, b1);
        }
    }
    __syncthreads();  // everyone done reading As/Bs

    // stage gi into S[128][196]
#pragma unroll
    for (int mt = 0; mt < 2; mt++) {
#pragma unroll
        for (int nt = 0; nt < 12; nt++) {
            int col = warp_n * 96 + nt * 8 + tig * 2;
            int r0 = warp_m * 32 + mt * 16 + gid;
            *(float2*)&S[r0 * G2B_PITCH + col] = make_float2(acc[mt][nt][0], acc[mt][nt][1]);
            *(float2*)&S[(r0 + 8) * G2B_PITCH + col] = make_float2(acc[mt][nt][2], acc[mt][nt][3]);
        }
    }
    __syncthreads();

    // GRU epilogue
    for (int idx = tid; idx < 128 * 64; idx += 256) {
        int r = idx >> 6;
        int o = idx & 63;
        int node = m0 + r;
        if (node >= N_NODES) continue;
        const float* gh = g_P + (size_t)node * PCOLS + 832;
        float ir = S[r * G2B_PITCH + o]        + sbih[o];
        float iz = S[r * G2B_PITCH + 64 + o]   + sbih[64 + o];
        float in_ = S[r * G2B_PITCH + 128 + o] + sbih[128 + o];
        float hr = gh[o]        + sbhh[o];
        float hz = gh[64 + o]   + sbhh[64 + o];
        float hn = gh[128 + o]  + sbhh[128 + o];
        float rg = 1.0f / (1.0f + __expf(-(ir + hr)));
        float z  = 1.0f / (1.0f + __expf(-(iz + hz)));
        float nn = tanhf(in_ + rg * hn);
        float xv = x[(size_t)node * 64 + o];
        out[(size_t)node * 64 + o] = (1.0f - z) * nn + z * xv;
    }
}

// ---------------- host ----------------
extern "C" void kernel_launch(void* const* d_in, const int* in_sizes, int n_in,
                              void* d_out, int out_size) {
    const float* x     = (const float*)d_in[0];
    const int*   ei    = (const int*)d_in[1];
    const float* ea    = (const float*)d_in[2];
    const float* gamma = (const float*)d_in[3];
    const float* beta  = (const float*)d_in[4];
    const float* lw    = (const float*)d_in[5];
    const float* lb    = (const float*)d_in[6];
    const float* wih   = (const float*)d_in[7];
    const float* whh   = (const float*)d_in[8];
    const float* bih   = (const float*)d_in[9];
    const float* bhh   = (const float*)d_in[10];
    float* out = (float*)d_out;

    cudaFuncSetAttribute(k_gemm1, cudaFuncAttributeMaxDynamicSharedMemorySize, G1_SMEM);
    cudaFuncSetAttribute(k_gemm2_gru, cudaFuncAttributeMaxDynamicSharedMemorySize, G2_SMEM);

    k_bn_reduce<<<BN_BLOCKS, 256>>>(ea);
    k_bn_fin<<<1, 32>>>(gamma, beta);

    dim3 g1((N_NODES + 127) / 128, PCOLS / 128);
    k_gemm1<<<g1, 256, G1_SMEM>>>(x, lw, lb, whh);

    k_edge<<<(N_EDGES * 32) / 256, 256>>>(ea, ei);

    k_gemm2_gru<<<(N_NODES + 127) / 128, 256, G2_SMEM>>>(x, wih, bih, bhh, out);
}

// round 5
// speedup vs baseline: 2.0193x; 2.0193x over previous
#include <cuda_runtime.h>
#include <cuda_fp16.h>
#include <math.h>

#define N_NODES 20000
#define N_EDGES 80000
#define DIM 64
#define EDIM 12
#define PCOLS 1024   // 12*64 W blocks + 64 bias block + 192 gh (x @ w_hh^T)
#define BCOLS 1216   // PCOLS + 192 (w_ih^T for the gi GEMM)
#define BN_EPS 1e-5f
#define BN_BLOCKS 160

// ---------------- scratch ----------------
__device__ __half g_Ph[(size_t)N_NODES * PCOLS]; // 41 MB fp16 P
__device__ float g_B[64 * BCOLS];                // packed tf32 weight matrix
__device__ float g_M[(size_t)N_NODES * DIM];     // relu(agg)/cnt
__device__ float g_GI[(size_t)N_NODES * 192];    // m @ w_ih^T
__device__ float g_agg[(size_t)N_NODES * DIM];
__device__ float g_cnt[N_NODES];
__device__ float g_bnpart[BN_BLOCKS * 2 * EDIM];
__device__ float g_scale[EDIM];
__device__ float g_shift[EDIM];

__device__ __forceinline__ float f2tf32(float f) {
    unsigned u;
    asm("cvt.rna.tf32.f32 %0, %1;" : "=r"(u) : "f"(f));
    return __uint_as_float(u);
}

// ---------------- kernel 1: pack B (tf32) + zero agg/cnt ----------------
// cols 0..767   : B[i][k*64+o] = lin_w[k, i*64+o]
// cols 768..831 : B[i][768+o]  = lin_b[i*64+o]
// cols 832..1023: B[i][832+g]  = w_hh[g, i]
// cols 1024..1215: B[i][1024+g] = w_ih[g, i]
__global__ void k_pack_zero(const float* __restrict__ lw, const float* __restrict__ lb,
                            const float* __restrict__ whh, const float* __restrict__ wih) {
    int idx = blockIdx.x * blockDim.x + threadIdx.x;
    int stride = gridDim.x * blockDim.x;

    float4* aggz = (float4*)g_agg;
    for (int j = idx; j < N_NODES * DIM / 4; j += stride)
        aggz[j] = make_float4(0.f, 0.f, 0.f, 0.f);
    for (int j = idx; j < N_NODES; j += stride) g_cnt[j] = 0.f;

    for (int t = idx; t < 64 * BCOLS; t += stride) {
        int i = t / BCOLS;
        int j = t % BCOLS;
        float v;
        if (j < 768) {
            int k = j >> 6, o = j & 63;
            v = lw[(size_t)k * 4096 + i * 64 + o];
        } else if (j < 832) {
            v = lb[i * 64 + (j - 768)];
        } else if (j < 1024) {
            v = whh[(j - 832) * 64 + i];
        } else {
            v = wih[(j - 1024) * 64 + i];
        }
        g_B[t] = f2tf32(v);
    }
}

// ---------------- kernel 2: BN per-block partial sums ----------------
__global__ void k_bn_reduce(const float* __restrict__ ea) {
    int idx = blockIdx.x * blockDim.x + threadIdx.x;
    int stride = gridDim.x * blockDim.x;
    float s[EDIM], q[EDIM];
#pragma unroll
    for (int c = 0; c < EDIM; c++) { s[c] = 0.f; q[c] = 0.f; }
    for (int e = idx; e < N_EDGES; e += stride) {
        const float* row = ea + (size_t)e * EDIM;
#pragma unroll
        for (int c = 0; c < EDIM; c++) { float v = row[c]; s[c] += v; q[c] += v * v; }
    }
#pragma unroll
    for (int off = 16; off > 0; off >>= 1) {
#pragma unroll
        for (int c = 0; c < EDIM; c++) {
            s[c] += __shfl_down_sync(0xffffffffu, s[c], off);
            q[c] += __shfl_down_sync(0xffffffffu, q[c], off);
        }
    }
    __shared__ float bs[2 * EDIM];
    if (threadIdx.x < 2 * EDIM) bs[threadIdx.x] = 0.f;
    __syncthreads();
    if ((threadIdx.x & 31) == 0) {
#pragma unroll
        for (int c = 0; c < EDIM; c++) {
            atomicAdd(&bs[c], s[c]);
            atomicAdd(&bs[EDIM + c], q[c]);
        }
    }
    __syncthreads();
    if (threadIdx.x < 2 * EDIM)
        g_bnpart[blockIdx.x * 2 * EDIM + threadIdx.x] = bs[threadIdx.x];
}

// ---------------- kernel 3: BN finalize ----------------
__global__ void k_bn_fin(const float* __restrict__ gamma, const float* __restrict__ beta) {
    int t = threadIdx.x;
    __shared__ float red[2 * EDIM];
    if (t < 2 * EDIM) {
        float acc = 0.f;
        for (int b = 0; b < BN_BLOCKS; b++) acc += g_bnpart[b * 2 * EDIM + t];
        red[t] = acc;
    }
    __syncwarp();
    if (t < EDIM) {
        float inv_n = 1.0f / (float)N_EDGES;
        float mu = red[t] * inv_n;
        float var = red[EDIM + t] * inv_n - mu * mu;
        float sc = rsqrtf(var + BN_EPS) * gamma[t];
        g_scale[t] = sc;
        g_shift[t] = beta[t] - mu * sc;
    }
}

// ---------------- mma helper ----------------
__device__ __forceinline__ void mma_tf32(float* c, const unsigned* a, unsigned b0, unsigned b1) {
    asm volatile(
        "mma.sync.aligned.m16n8k8.row.col.f32.tf32.tf32.f32 "
        "{%0,%1,%2,%3}, {%4,%5,%6,%7}, {%8,%9}, {%0,%1,%2,%3};"
        : "+f"(c[0]), "+f"(c[1]), "+f"(c[2]), "+f"(c[3])
        : "r"(a[0]), "r"(a[1]), "r"(a[2]), "r"(a[3]), "r"(b0), "r"(b1));
}

#define GA_PITCH 68
#define GB_PITCH 132
#define GEMM_SMEM ((128 * GA_PITCH + 64 * GB_PITCH) * 4)

// ---------------- kernel 4: GEMM1  P(half) = X @ B[:, 0:1024] ----------------
__global__ void k_gemm1(const float* __restrict__ x) {
    extern __shared__ float sm[];
    float* As = sm;                    // [128][68]
    float* Bs = sm + 128 * GA_PITCH;   // [64][132]

    int tid = threadIdx.x;
    int m0 = blockIdx.x * 128;
    int n0 = blockIdx.y * 128;

#pragma unroll
    for (int r = 0; r < 8; r++) {
        int id = r * 256 + tid;
        int m = id >> 4;
        int k4 = (id & 15) << 2;
        float4 v = make_float4(0.f, 0.f, 0.f, 0.f);
        if (m0 + m < N_NODES) v = *(const float4*)&x[(size_t)(m0 + m) * 64 + k4];
        v.x = f2tf32(v.x); v.y = f2tf32(v.y); v.z = f2tf32(v.z); v.w = f2tf32(v.w);
        *(float4*)&As[m * GA_PITCH + k4] = v;
    }
#pragma unroll
    for (int r = 0; r < 8; r++) {
        int id = r * 256 + tid;
        int k = id >> 5;
        int n4 = (id & 31) << 2;
        float4 v = *(const float4*)&g_B[(size_t)k * BCOLS + n0 + n4];
        *(float4*)&Bs[k * GB_PITCH + n4] = v;
    }
    __syncthreads();

    int wid = tid >> 5;
    int lane = tid & 31;
    int gid = lane >> 2;
    int tig = lane & 3;
    int warp_m = wid & 3;
    int warp_n = wid >> 2;

    float acc[2][8][4];
#pragma unroll
    for (int mt = 0; mt < 2; mt++)
#pragma unroll
        for (int nt = 0; nt < 8; nt++)
#pragma unroll
            for (int j = 0; j < 4; j++) acc[mt][nt][j] = 0.f;

#pragma unroll
    for (int ks = 0; ks < 8; ks++) {
        int k0 = ks * 8;
        unsigned a[2][4];
#pragma unroll
        for (int mt = 0; mt < 2; mt++) {
            int rowb = warp_m * 32 + mt * 16;
            a[mt][0] = __float_as_uint(As[(rowb + gid) * GA_PITCH + k0 + tig]);
            a[mt][1] = __float_as_uint(As[(rowb + gid + 8) * GA_PITCH + k0 + tig]);
            a[mt][2] = __float_as_uint(As[(rowb + gid) * GA_PITCH + k0 + tig + 4]);
            a[mt][3] = __float_as_uint(As[(rowb + gid + 8) * GA_PITCH + k0 + tig + 4]);
        }
#pragma unroll
        for (int nt = 0; nt < 8; nt++) {
            int nb = warp_n * 64 + nt * 8 + gid;
            unsigned b0 = __float_as_uint(Bs[(k0 + tig) * GB_PITCH + nb]);
            unsigned b1 = __float_as_uint(Bs[(k0 + tig + 4) * GB_PITCH + nb]);
            mma_tf32(acc[0][nt], a[0], b0, b1);
            mma_tf32(acc[1][nt], a[1], b0, b1);
        }
    }

#pragma unroll
    for (int mt = 0; mt < 2; mt++) {
#pragma unroll
        for (int nt = 0; nt < 8; nt++) {
            int col = n0 + warp_n * 64 + nt * 8 + tig * 2;
            int r0 = m0 + warp_m * 32 + mt * 16 + gid;
            if (r0 < N_NODES)
                *(half2*)&g_Ph[(size_t)r0 * PCOLS + col] =
                    __floats2half2_rn(acc[mt][nt][0], acc[mt][nt][1]);
            int r1 = r0 + 8;
            if (r1 < N_NODES)
                *(half2*)&g_Ph[(size_t)r1 * PCOLS + col] =
                    __floats2half2_rn(acc[mt][nt][2], acc[mt][nt][3]);
        }
    }
}

// ---------------- kernel 5: per-edge message + scatter (fp16 gather) ----------------
__global__ void k_edge(const float* __restrict__ ea, const int* __restrict__ ei) {
    int wg = (blockIdx.x * blockDim.x + threadIdx.x) >> 5;
    int lane = threadIdx.x & 31;
    if (wg >= N_EDGES) return;
    int e = wg;
    int src = ei[e];
    int dst = ei[N_EDGES + e];

    float eb = 0.f;
    if (lane < EDIM) eb = ea[(size_t)e * EDIM + lane] * g_scale[lane] + g_shift[lane];

    const half2* p2 = (const half2*)(g_Ph + (size_t)src * PCOLS);
    float2 acc = __half22float2(p2[384 + lane]);  // bias block at col 768
#pragma unroll
    for (int k = 0; k < EDIM; k++) {
        float c = __shfl_sync(0xffffffffu, eb, k);
        float2 w = __half22float2(p2[k * 32 + lane]);
        acc.x += c * w.x;
        acc.y += c * w.y;
    }
    float* a = g_agg + (size_t)dst * DIM + 2 * lane;
    atomicAdd(a, acc.x);
    atomicAdd(a + 1, acc.y);
    if (lane == 0) atomicAdd(&g_cnt[dst], 1.0f);
}

// ---------------- kernel 6: m = relu(agg)/max(cnt,1) ----------------
__global__ void k_mrelu() {
    int idx = blockIdx.x * blockDim.x + threadIdx.x;
    if (idx >= N_NODES * DIM) return;
    int n = idx >> 6;
    float c = fmaxf(g_cnt[n], 1.0f);
    g_M[idx] = fmaxf(g_agg[idx], 0.f) / c;
}

// ---------------- kernel 7: GEMM2  GI = M @ B[:, 1024:1216] ----------------
__global__ void k_gemm2() {
    extern __shared__ float sm[];
    float* As = sm;
    float* Bs = sm + 128 * GA_PITCH;
    const float* A = g_M;
    const float* Bg = g_B + 1024;
    const int Ncols = 192;

    int tid = threadIdx.x;
    int m0 = blockIdx.x * 128;
    int n0 = blockIdx.y * 128;

#pragma unroll
    for (int r = 0; r < 8; r++) {
        int id = r * 256 + tid;
        int m = id >> 4;
        int k4 = (id & 15) << 2;
        float4 v = make_float4(0.f, 0.f, 0.f, 0.f);
        if (m0 + m < N_NODES) v = *(const float4*)&A[(size_t)(m0 + m) * 64 + k4];
        v.x = f2tf32(v.x); v.y = f2tf32(v.y); v.z = f2tf32(v.z); v.w = f2tf32(v.w);
        *(float4*)&As[m * GA_PITCH + k4] = v;
    }
#pragma unroll
    for (int r = 0; r < 8; r++) {
        int id = r * 256 + tid;
        int k = id >> 5;
        int n4 = (id & 31) << 2;
        float4 v = make_float4(0.f, 0.f, 0.f, 0.f);
        if (n0 + n4 < Ncols) v = *(const float4*)&Bg[(size_t)k * BCOLS + n0 + n4];
        *(float4*)&Bs[k * GB_PITCH + n4] = v;
    }
    __syncthreads();

    int wid = tid >> 5;
    int lane = tid & 31;
    int gid = lane >> 2;
    int tig = lane & 3;
    int warp_m = wid & 3;
    int warp_n = wid >> 2;

    float acc[2][8][4];
#pragma unroll
    for (int mt = 0; mt < 2; mt++)
#pragma unroll
        for (int nt = 0; nt < 8; nt++)
#pragma unroll
            for (int j = 0; j < 4; j++) acc[mt][nt][j] = 0.f;

#pragma unroll
    for (int ks = 0; ks < 8; ks++) {
        int k0 = ks * 8;
        unsigned a[2][4];
#pragma unroll
        for (int mt = 0; mt < 2; mt++) {
            int rowb = warp_m * 32 + mt * 16;
            a[mt][0] = __float_as_uint(As[(rowb + gid) * GA_PITCH + k0 + tig]);
            a[mt][1] = __float_as_uint(As[(rowb + gid + 8) * GA_PITCH + k0 + tig]);
            a[mt][2] = __float_as_uint(As[(rowb + gid) * GA_PITCH + k0 + tig + 4]);
            a[mt][3] = __float_as_uint(As[(rowb + gid + 8) * GA_PITCH + k0 + tig + 4]);
        }
#pragma unroll
        for (int nt = 0; nt < 8; nt++) {
            int nb = warp_n * 64 + nt * 8 + gid;
            unsigned b0 = __float_as_uint(Bs[(k0 + tig) * GB_PITCH + nb]);
            unsigned b1 = __float_as_uint(Bs[(k0 + tig + 4) * GB_PITCH + nb]);
            mma_tf32(acc[0][nt], a[0], b0, b1);
            mma_tf32(acc[1][nt], a[1], b0, b1);
        }
    }

#pragma unroll
    for (int mt = 0; mt < 2; mt++) {
#pragma unroll
        for (int nt = 0; nt < 8; nt++) {
            int col = n0 + warp_n * 64 + nt * 8 + tig * 2;
            if (col >= Ncols) continue;
            int r0 = m0 + warp_m * 32 + mt * 16 + gid;
            if (r0 < N_NODES)
                *(float2*)&g_GI[(size_t)r0 * 192 + col] = make_float2(acc[mt][nt][0], acc[mt][nt][1]);
            int r1 = r0 + 8;
            if (r1 < N_NODES)
                *(float2*)&g_GI[(size_t)r1 * 192 + col] = make_float2(acc[mt][nt][2], acc[mt][nt][3]);
        }
    }
}

// ---------------- kernel 8: elementwise GRU ----------------
__global__ void k_out(const float* __restrict__ x,
                      const float* __restrict__ bih, const float* __restrict__ bhh,
                      float* __restrict__ out) {
    int idx = blockIdx.x * blockDim.x + threadIdx.x;
    if (idx >= N_NODES * DIM) return;
    int n = idx >> 6;
    int o = idx & 63;

    const float* gi = g_GI + (size_t)n * 192;
    const __half* gh = g_Ph + (size_t)n * PCOLS + 832;

    float ir = gi[o] + bih[o];
    float iz = gi[64 + o] + bih[64 + o];
    float in_ = gi[128 + o] + bih[128 + o];
    float hr = __half2float(gh[o]) + bhh[o];
    float hz = __half2float(gh[64 + o]) + bhh[64 + o];
    float hn = __half2float(gh[128 + o]) + bhh[128 + o];

    float r = 1.0f / (1.0f + __expf(-(ir + hr)));
    float z = 1.0f / (1.0f + __expf(-(iz + hz)));
    float nn = tanhf(in_ + r * hn);
    float xv = x[idx];
    out[idx] = (1.0f - z) * nn + z * xv;
}

// ---------------- host ----------------
extern "C" void kernel_launch(void* const* d_in, const int* in_sizes, int n_in,
                              void* d_out, int out_size) {
    const float* x     = (const float*)d_in[0];
    const int*   ei    = (const int*)d_in[1];
    const float* ea    = (const float*)d_in[2];
    const float* gamma = (const float*)d_in[3];
    const float* beta  = (const float*)d_in[4];
    const float* lw    = (const float*)d_in[5];
    const float* lb    = (const float*)d_in[6];
    const float* wih   = (const float*)d_in[7];
    const float* whh   = (const float*)d_in[8];
    const float* bih   = (const float*)d_in[9];
    const float* bhh   = (const float*)d_in[10];
    float* out = (float*)d_out;

    cudaFuncSetAttribute(k_gemm1, cudaFuncAttributeMaxDynamicSharedMemorySize, GEMM_SMEM);
    cudaFuncSetAttribute(k_gemm2, cudaFuncAttributeMaxDynamicSharedMemorySize, GEMM_SMEM);

    k_pack_zero<<<512, 256>>>(lw, lb, whh, wih);
    k_bn_reduce<<<BN_BLOCKS, 256>>>(ea);
    k_bn_fin<<<1, 32>>>(gamma, beta);

    dim3 g1((N_NODES + 127) / 128, PCOLS / 128);
    k_gemm1<<<g1, 256, GEMM_SMEM>>>(x);

    k_edge<<<(N_EDGES * 32) / 256, 256>>>(ea, ei);
    k_mrelu<<<(N_NODES * DIM + 255) / 256, 256>>>();

    dim3 g2((N_NODES + 127) / 128, 2);
    k_gemm2<<<g2, 256, GEMM_SMEM>>>();

    k_out<<<(N_NODES * DIM + 255) / 256, 256>>>(x, bih, bhh, out);
}

// round 6
// speedup vs baseline: 2.1826x; 1.0809x over previous
#include <cuda_runtime.h>
#include <cuda_fp16.h>
#include <math.h>

#define N_NODES 20000
#define N_EDGES 80000
#define DIM 64
#define EDIM 12
#define PCOLS 1024   // 12*64 W blocks + 64 bias block + 192 gh (x @ w_hh^T)
#define BCOLS 1216
#define BN_EPS 1e-5f
#define BN_BLOCKS 160

// ---------------- scratch ----------------
__device__ __half g_Ph[(size_t)N_NODES * PCOLS]; // 41 MB fp16 P
__device__ __half g_Bh[1024 * 64];               // B^T fp16: [j][k] for gemm1
__device__ float g_B[64 * BCOLS];                // tf32 B (only cols 1024..1215 used, gemm2)
__device__ float g_GI[(size_t)N_NODES * 192];    // m @ w_ih^T
__device__ float g_agg[(size_t)N_NODES * DIM];
__device__ float g_cnt[N_NODES];
__device__ float g_bnpart[BN_BLOCKS * 2 * EDIM];
__device__ float g_scale[EDIM];
__device__ float g_shift[EDIM];

__device__ __forceinline__ float f2tf32(float f) {
    unsigned u;
    asm("cvt.rna.tf32.f32 %0, %1;" : "=r"(u) : "f"(f));
    return __uint_as_float(u);
}

// ---------------- kernel 1: pack weights + zero agg/cnt ----------------
// g_Bh[j*64+i] = B[i][j]:
//   j<768: lin_w[j>>6, i*64 + (j&63)]; 768..831: lin_b[i*64+j-768]; 832..1023: w_hh[j-832, i]
// g_B[i*BCOLS + 1024 + g] = w_ih[g, i]  (tf32, gemm2)
__global__ void k_pack_zero(const float* __restrict__ lw, const float* __restrict__ lb,
                            const float* __restrict__ whh, const float* __restrict__ wih) {
    int idx = blockIdx.x * blockDim.x + threadIdx.x;
    int stride = gridDim.x * blockDim.x;

    float4* aggz = (float4*)g_agg;
    for (int j = idx; j < N_NODES * DIM / 4; j += stride)
        aggz[j] = make_float4(0.f, 0.f, 0.f, 0.f);
    for (int j = idx; j < N_NODES; j += stride) g_cnt[j] = 0.f;

    for (int t = idx; t < 1024 * 64; t += stride) {
        int j = t >> 6, i = t & 63;
        float v;
        if (j < 768) {
            v = lw[(size_t)(j >> 6) * 4096 + i * 64 + (j & 63)];
        } else if (j < 832) {
            v = lb[i * 64 + (j - 768)];
        } else {
            v = whh[(j - 832) * 64 + i];
        }
        g_Bh[t] = __float2half_rn(v);
    }
    for (int t = idx; t < 64 * 192; t += stride) {
        int i = t / 192, g = t % 192;
        g_B[(size_t)i * BCOLS + 1024 + g] = f2tf32(wih[g * 64 + i]);
    }
}

// ---------------- kernel 2: BN per-block partial sums ----------------
__global__ void k_bn_reduce(const float* __restrict__ ea) {
    int idx = blockIdx.x * blockDim.x + threadIdx.x;
    int stride = gridDim.x * blockDim.x;
    float s[EDIM], q[EDIM];
#pragma unroll
    for (int c = 0; c < EDIM; c++) { s[c] = 0.f; q[c] = 0.f; }
    for (int e = idx; e < N_EDGES; e += stride) {
        const float* row = ea + (size_t)e * EDIM;
#pragma unroll
        for (int c = 0; c < EDIM; c++) { float v = row[c]; s[c] += v; q[c] += v * v; }
    }
#pragma unroll
    for (int off = 16; off > 0; off >>= 1) {
#pragma unroll
        for (int c = 0; c < EDIM; c++) {
            s[c] += __shfl_down_sync(0xffffffffu, s[c], off);
            q[c] += __shfl_down_sync(0xffffffffu, q[c], off);
        }
    }
    __shared__ float bs[2 * EDIM];
    if (threadIdx.x < 2 * EDIM) bs[threadIdx.x] = 0.f;
    __syncthreads();
    if ((threadIdx.x & 31) == 0) {
#pragma unroll
        for (int c = 0; c < EDIM; c++) {
            atomicAdd(&bs[c], s[c]);
            atomicAdd(&bs[EDIM + c], q[c]);
        }
    }
    __syncthreads();
    if (threadIdx.x < 2 * EDIM)
        g_bnpart[blockIdx.x * 2 * EDIM + threadIdx.x] = bs[threadIdx.x];
}

// ---------------- kernel 3: BN finalize ----------------
__global__ void k_bn_fin(const float* __restrict__ gamma, const float* __restrict__ beta) {
    int t = threadIdx.x;
    __shared__ float red[2 * EDIM];
    if (t < 2 * EDIM) {
        float acc = 0.f;
        for (int b = 0; b < BN_BLOCKS; b++) acc += g_bnpart[b * 2 * EDIM + t];
        red[t] = acc;
    }
    __syncwarp();
    if (t < EDIM) {
        float inv_n = 1.0f / (float)N_EDGES;
        float mu = red[t] * inv_n;
        float var = red[EDIM + t] * inv_n - mu * mu;
        float sc = rsqrtf(var + BN_EPS) * gamma[t];
        g_scale[t] = sc;
        g_shift[t] = beta[t] - mu * sc;
    }
}

// ---------------- fp16 mma helpers ----------------
__device__ __forceinline__ void mma_f16(float* c, const unsigned* a, unsigned b0, unsigned b1) {
    asm volatile(
        "mma.sync.aligned.m16n8k16.row.col.f32.f16.f16.f32 "
        "{%0,%1,%2,%3}, {%4,%5,%6,%7}, {%8,%9}, {%0,%1,%2,%3};"
        : "+f"(c[0]), "+f"(c[1]), "+f"(c[2]), "+f"(c[3])
        : "r"(a[0]), "r"(a[1]), "r"(a[2]), "r"(a[3]), "r"(b0), "r"(b1));
}

__device__ __forceinline__ void ldsm_x4(unsigned* r, unsigned addr) {
    asm volatile("ldmatrix.sync.aligned.m8n8.x4.shared.b16 {%0,%1,%2,%3}, [%4];"
                 : "=r"(r[0]), "=r"(r[1]), "=r"(r[2]), "=r"(r[3]) : "r"(addr));
}

// ---------------- kernel 4: GEMM1 fp16  P(half) = X @ B[:, 0:1024] ----------------
// Tiles: BM=128, BN=128, K=64. 256 thr, 8 warps (4m x 2n). smem 32KB, XOR-swizzled.
#define G1_SMEM (2 * 128 * 64 * 2)

__global__ void k_gemm1(const float* __restrict__ x) {
    extern __shared__ char smraw[];
    __half* As = (__half*)smraw;             // [128][64] halves, 16B-chunk swizzle
    __half* Bs = (__half*)smraw + 128 * 64;  // [128 j][64 k] halves, swizzled

    int tid = threadIdx.x;
    int m0 = blockIdx.x * 128;
    int n0 = blockIdx.y * 128;

    // A tile: 128 rows x 8 chunks(16B = 8 halves)
#pragma unroll
    for (int r = 0; r < 4; r++) {
        int id = r * 256 + tid;
        int m = id >> 3, c = id & 7;
        float4 v0 = make_float4(0.f, 0.f, 0.f, 0.f), v1 = v0;
        if (m0 + m < N_NODES) {
            const float* px = &x[(size_t)(m0 + m) * 64 + c * 8];
            v0 = *(const float4*)px;
            v1 = *(const float4*)(px + 4);
        }
        half2 h[4] = {__floats2half2_rn(v0.x, v0.y), __floats2half2_rn(v0.z, v0.w),
                      __floats2half2_rn(v1.x, v1.y), __floats2half2_rn(v1.z, v1.w)};
        *(uint4*)&As[m * 64 + ((c ^ (m & 7)) << 3)] = *(uint4*)h;
    }
    // B tile: rows j = n0..n0+127, 8 chunks each, from g_Bh
#pragma unroll
    for (int r = 0; r < 4; r++) {
        int id = r * 256 + tid;
        int j = id >> 3, c = id & 7;
        uint4 v = *(const uint4*)&g_Bh[(size_t)(n0 + j) * 64 + c * 8];
        *(uint4*)&Bs[j * 64 + ((c ^ (j & 7)) << 3)] = v;
    }
    __syncthreads();

    int wid = tid >> 5;
    int lane = tid & 31;
    int warp_m = wid & 3;      // 32 rows
    int warp_n = wid >> 2;     // 64 cols
    int lrow = lane & 15;
    int lsel = lane >> 4;

    unsigned a_base = (unsigned)__cvta_generic_to_shared(As);
    unsigned b_base = (unsigned)__cvta_generic_to_shared(Bs);

    float acc[2][8][4];
#pragma unroll
    for (int mt = 0; mt < 2; mt++)
#pragma unroll
        for (int nt = 0; nt < 8; nt++)
#pragma unroll
            for (int j = 0; j < 4; j++) acc[mt][nt][j] = 0.f;

#pragma unroll
    for (int ks = 0; ks < 4; ks++) {
        int chunk = ks * 2 + lsel;
        unsigned a[2][4];
#pragma unroll
        for (int mt = 0; mt < 2; mt++) {
            int row = warp_m * 32 + mt * 16 + lrow;
            ldsm_x4(a[mt], a_base + (row * 64 + ((chunk ^ (row & 7)) << 3)) * 2);
        }
#pragma unroll
        for (int nt2 = 0; nt2 < 4; nt2++) {
            int row = warp_n * 64 + nt2 * 16 + lrow;
            unsigned b[4];
            ldsm_x4(b, b_base + (row * 64 + ((chunk ^ (row & 7)) << 3)) * 2);
            mma_f16(acc[0][nt2 * 2],     a[0], b[0], b[2]);
            mma_f16(acc[0][nt2 * 2 + 1], a[0], b[1], b[3]);
            mma_f16(acc[1][nt2 * 2],     a[1], b[0], b[2]);
            mma_f16(acc[1][nt2 * 2 + 1], a[1], b[1], b[3]);
        }
    }

    int gid = lane >> 2;
    int tig = lane & 3;
#pragma unroll
    for (int mt = 0; mt < 2; mt++) {
#pragma unroll
        for (int nt = 0; nt < 8; nt++) {
            int col = n0 + warp_n * 64 + nt * 8 + tig * 2;
            int r0 = m0 + warp_m * 32 + mt * 16 + gid;
            if (r0 < N_NODES)
                *(half2*)&g_Ph[(size_t)r0 * PCOLS + col] =
                    __floats2half2_rn(acc[mt][nt][0], acc[mt][nt][1]);
            int r1 = r0 + 8;
            if (r1 < N_NODES)
                *(half2*)&g_Ph[(size_t)r1 * PCOLS + col] =
                    __floats2half2_rn(acc[mt][nt][2], acc[mt][nt][3]);
        }
    }
}

// ---------------- kernel 5: per-edge message + scatter (fp16 gather) ----------------
__global__ void k_edge(const float* __restrict__ ea, const int* __restrict__ ei) {
    int wg = (blockIdx.x * blockDim.x + threadIdx.x) >> 5;
    int lane = threadIdx.x & 31;
    if (wg >= N_EDGES) return;
    int e = wg;
    int src = ei[e];
    int dst = ei[N_EDGES + e];

    float eb = 0.f;
    if (lane < EDIM) eb = ea[(size_t)e * EDIM + lane] * g_scale[lane] + g_shift[lane];

    const half2* p2 = (const half2*)(g_Ph + (size_t)src * PCOLS);
    float2 acc = __half22float2(p2[384 + lane]);  // bias block at col 768
#pragma unroll
    for (int k = 0; k < EDIM; k++) {
        float c = __shfl_sync(0xffffffffu, eb, k);
        float2 w = __half22float2(p2[k * 32 + lane]);
        acc.x += c * w.x;
        acc.y += c * w.y;
    }
    float* a = g_agg + (size_t)dst * DIM + 2 * lane;
    atomicAdd(a, acc.x);
    atomicAdd(a + 1, acc.y);
    if (lane == 0) atomicAdd(&g_cnt[dst], 1.0f);
}

// ---------------- mma tf32 (gemm2) ----------------
__device__ __forceinline__ void mma_tf32(float* c, const unsigned* a, unsigned b0, unsigned b1) {
    asm volatile(
        "mma.sync.aligned.m16n8k8.row.col.f32.tf32.tf32.f32 "
        "{%0,%1,%2,%3}, {%4,%5,%6,%7}, {%8,%9}, {%0,%1,%2,%3};"
        : "+f"(c[0]), "+f"(c[1]), "+f"(c[2]), "+f"(c[3])
        : "r"(a[0]), "r"(a[1]), "r"(a[2]), "r"(a[3]), "r"(b0), "r"(b1));
}

#define GA_PITCH 68
#define GB_PITCH 132
#define G2_SMEM ((128 * GA_PITCH + 64 * GB_PITCH) * 4)

// ---------------- kernel 6: GEMM2  GI = relu(agg)/cnt @ B[:, 1024:1216] ----------------
__global__ void k_gemm2() {
    extern __shared__ char smraw[];
    float* As = (float*)smraw;
    float* Bs = (float*)smraw + 128 * GA_PITCH;
    const float* Bg = g_B + 1024;
    const int Ncols = 192;

    int tid = threadIdx.x;
    int m0 = blockIdx.x * 128;
    int n0 = blockIdx.y * 128;

#pragma unroll
    for (int r = 0; r < 8; r++) {
        int id = r * 256 + tid;
        int m = id >> 4;
        int k4 = (id & 15) << 2;
        float4 v = make_float4(0.f, 0.f, 0.f, 0.f);
        int node = m0 + m;
        if (node < N_NODES) {
            float inv = 1.0f / fmaxf(g_cnt[node], 1.0f);
            float4 a = *(const float4*)&g_agg[(size_t)node * 64 + k4];
            v.x = fmaxf(a.x, 0.f) * inv;
            v.y = fmaxf(a.y, 0.f) * inv;
            v.z = fmaxf(a.z, 0.f) * inv;
            v.w = fmaxf(a.w, 0.f) * inv;
        }
        v.x = f2tf32(v.x); v.y = f2tf32(v.y); v.z = f2tf32(v.z); v.w = f2tf32(v.w);
        *(float4*)&As[m * GA_PITCH + k4] = v;
    }
#pragma unroll
    for (int r = 0; r < 8; r++) {
        int id = r * 256 + tid;
        int k = id >> 5;
        int n4 = (id & 31) << 2;
        float4 v = make_float4(0.f, 0.f, 0.f, 0.f);
        if (n0 + n4 < Ncols) v = *(const float4*)&Bg[(size_t)k * BCOLS + n0 + n4];
        *(float4*)&Bs[k * GB_PITCH + n4] = v;
    }
    __syncthreads();

    int wid = tid >> 5;
    int lane = tid & 31;
    int gid = lane >> 2;
    int tig = lane & 3;
    int warp_m = wid & 3;
    int warp_n = wid >> 2;

    float acc[2][8][4];
#pragma unroll
    for (int mt = 0; mt < 2; mt++)
#pragma unroll
        for (int nt = 0; nt < 8; nt++)
#pragma unroll
            for (int j = 0; j < 4; j++) acc[mt][nt][j] = 0.f;

#pragma unroll
    for (int ks = 0; ks < 8; ks++) {
        int k0 = ks * 8;
        unsigned a[2][4];
#pragma unroll
        for (int mt = 0; mt < 2; mt++) {
            int rowb = warp_m * 32 + mt * 16;
            a[mt][0] = __float_as_uint(As[(rowb + gid) * GA_PITCH + k0 + tig]);
            a[mt][1] = __float_as_uint(As[(rowb + gid + 8) * GA_PITCH + k0 + tig]);
            a[mt][2] = __float_as_uint(As[(rowb + gid) * GA_PITCH + k0 + tig + 4]);
            a[mt][3] = __float_as_uint(As[(rowb + gid + 8) * GA_PITCH + k0 + tig + 4]);
        }
#pragma unroll
        for (int nt = 0; nt < 8; nt++) {
            int nb = warp_n * 64 + nt * 8 + gid;
            unsigned b0 = __float_as_uint(Bs[(k0 + tig) * GB_PITCH + nb]);
            unsigned b1 = __float_as_uint(Bs[(k0 + tig + 4) * GB_PITCH + nb]);
            mma_tf32(acc[0][nt], a[0], b0, b1);
            mma_tf32(acc[1][nt], a[1], b0, b1);
        }
    }

#pragma unroll
    for (int mt = 0; mt < 2; mt++) {
#pragma unroll
        for (int nt = 0; nt < 8; nt++) {
            int col = n0 + warp_n * 64 + nt * 8 + tig * 2;
            if (col >= Ncols) continue;
            int r0 = m0 + warp_m * 32 + mt * 16 + gid;
            if (r0 < N_NODES)
                *(float2*)&g_GI[(size_t)r0 * 192 + col] = make_float2(acc[mt][nt][0], acc[mt][nt][1]);
            int r1 = r0 + 8;
            if (r1 < N_NODES)
                *(float2*)&g_GI[(size_t)r1 * 192 + col] = make_float2(acc[mt][nt][2], acc[mt][nt][3]);
        }
    }
}

// ---------------- kernel 7: elementwise GRU ----------------
__global__ void k_out(const float* __restrict__ x,
                      const float* __restrict__ bih, const float* __restrict__ bhh,
                      float* __restrict__ out) {
    int idx = blockIdx.x * blockDim.x + threadIdx.x;
    if (idx >= N_NODES * DIM) return;
    int n = idx >> 6;
    int o = idx & 63;

    const float* gi = g_GI + (size_t)n * 192;
    const __half* gh = g_Ph + (size_t)n * PCOLS + 832;

    float ir = gi[o] + bih[o];
    float iz = gi[64 + o] + bih[64 + o];
    float in_ = gi[128 + o] + bih[128 + o];
    float hr = __half2float(gh[o]) + bhh[o];
    float hz = __half2float(gh[64 + o]) + bhh[64 + o];
    float hn = __half2float(gh[128 + o]) + bhh[128 + o];

    float r = 1.0f / (1.0f + __expf(-(ir + hr)));
    float z = 1.0f / (1.0f + __expf(-(iz + hz)));
    float nn = tanhf(in_ + r * hn);
    float xv = x[idx];
    out[idx] = (1.0f - z) * nn + z * xv;
}

// ---------------- host ----------------
extern "C" void kernel_launch(void* const* d_in, const int* in_sizes, int n_in,
                              void* d_out, int out_size) {
    const float* x     = (const float*)d_in[0];
    const int*   ei    = (const int*)d_in[1];
    const float* ea    = (const float*)d_in[2];
    const float* gamma = (const float*)d_in[3];
    const float* beta  = (const float*)d_in[4];
    const float* lw    = (const float*)d_in[5];
    const float* lb    = (const float*)d_in[6];
    const float* wih   = (const float*)d_in[7];
    const float* whh   = (const float*)d_in[8];
    const float* bih   = (const float*)d_in[9];
    const float* bhh   = (const float*)d_in[10];
    float* out = (float*)d_out;

    cudaFuncSetAttribute(k_gemm2, cudaFuncAttributeMaxDynamicSharedMemorySize, G2_SMEM);

    k_pack_zero<<<512, 256>>>(lw, lb, whh, wih);
    k_bn_reduce<<<BN_BLOCKS, 256>>>(ea);
    k_bn_fin<<<1, 32>>>(gamma, beta);

    dim3 g1((N_NODES + 127) / 128, PCOLS / 128);
    k_gemm1<<<g1, 256, G1_SMEM>>>(x);

    k_edge<<<(N_EDGES * 32) / 256, 256>>>(ea, ei);

    dim3 g2((N_NODES + 127) / 128, 2);
    k_gemm2<<<g2, 256, G2_SMEM>>>();

    k_out<<<(N_NODES * DIM + 255) / 256, 256>>>(x, bih, bhh, out);
}

// round 8
// speedup vs baseline: 2.3467x; 1.0752x over previous
#include <cuda_runtime.h>
#include <cuda_fp16.h>
#include <math.h>

#define N_NODES 20000
#define N_EDGES 80000
#define DIM 64
#define EDIM 12
#define PCOLS 1024   // 12*64 W blocks + 64 bias block + 192 gh (x @ w_hh^T)
#define BCOLS 1216
#define BN_EPS 1e-5f
#define BN_BLOCKS 160

// ---------------- scratch ----------------
__device__ __half g_Ph[(size_t)N_NODES * PCOLS]; // 41 MB fp16 P
__device__ __half g_Bh[1024 * 64];               // B^T fp16: [j][k] for gemm1
__device__ float g_B[64 * BCOLS];                // tf32 B (only cols 1024..1215 used, gemm2)
__device__ float g_GI[(size_t)N_NODES * 192];    // m @ w_ih^T
__device__ float g_agg[(size_t)N_NODES * DIM];
__device__ float g_cnt[N_NODES];
__device__ float g_bnpart[BN_BLOCKS * 2 * EDIM];
__device__ float g_scale[EDIM];
__device__ float g_shift[EDIM];

__device__ __forceinline__ float f2tf32(float f) {
    unsigned u;
    asm("cvt.rna.tf32.f32 %0, %1;" : "=r"(u) : "f"(f));
    return __uint_as_float(u);
}

// ---------------- kernel 1: pack weights + zero agg/cnt ----------------
__global__ void k_pack_zero(const float* __restrict__ lw, const float* __restrict__ lb,
                            const float* __restrict__ whh, const float* __restrict__ wih) {
    int idx = blockIdx.x * blockDim.x + threadIdx.x;
    int stride = gridDim.x * blockDim.x;

    float4* aggz = (float4*)g_agg;
    for (int j = idx; j < N_NODES * DIM / 4; j += stride)
        aggz[j] = make_float4(0.f, 0.f, 0.f, 0.f);
    for (int j = idx; j < N_NODES; j += stride) g_cnt[j] = 0.f;

    for (int t = idx; t < 1024 * 64; t += stride) {
        int j = t >> 6, i = t & 63;
        float v;
        if (j < 768) {
            v = lw[(size_t)(j >> 6) * 4096 + i * 64 + (j & 63)];
        } else if (j < 832) {
            v = lb[i * 64 + (j - 768)];
        } else {
            v = whh[(j - 832) * 64 + i];
        }
        g_Bh[t] = __float2half_rn(v);
    }
    for (int t = idx; t < 64 * 192; t += stride) {
        int i = t / 192, g = t % 192;
        g_B[(size_t)i * BCOLS + 1024 + g] = f2tf32(wih[g * 64 + i]);
    }
}

// ---------------- kernel 2: BN per-block partial sums ----------------
__global__ void k_bn_reduce(const float* __restrict__ ea) {
    int idx = blockIdx.x * blockDim.x + threadIdx.x;
    int stride = gridDim.x * blockDim.x;
    float s[EDIM], q[EDIM];
#pragma unroll
    for (int c = 0; c < EDIM; c++) { s[c] = 0.f; q[c] = 0.f; }
    for (int e = idx; e < N_EDGES; e += stride) {
        const float* row = ea + (size_t)e * EDIM;
#pragma unroll
        for (int c = 0; c < EDIM; c++) { float v = row[c]; s[c] += v; q[c] += v * v; }
    }
#pragma unroll
    for (int off = 16; off > 0; off >>= 1) {
#pragma unroll
        for (int c = 0; c < EDIM; c++) {
            s[c] += __shfl_down_sync(0xffffffffu, s[c], off);
            q[c] += __shfl_down_sync(0xffffffffu, q[c], off);
        }
    }
    __shared__ float bs[2 * EDIM];
    if (threadIdx.x < 2 * EDIM) bs[threadIdx.x] = 0.f;
    __syncthreads();
    if ((threadIdx.x & 31) == 0) {
#pragma unroll
        for (int c = 0; c < EDIM; c++) {
            atomicAdd(&bs[c], s[c]);
            atomicAdd(&bs[EDIM + c], q[c]);
        }
    }
    __syncthreads();
    if (threadIdx.x < 2 * EDIM)
        g_bnpart[blockIdx.x * 2 * EDIM + threadIdx.x] = bs[threadIdx.x];
}

// ---------------- kernel 3: BN finalize ----------------
__global__ void k_bn_fin(const float* __restrict__ gamma, const float* __restrict__ beta) {
    int t = threadIdx.x;
    __shared__ float red[2 * EDIM];
    if (t < 2 * EDIM) {
        float acc = 0.f;
        for (int b = 0; b < BN_BLOCKS; b++) acc += g_bnpart[b * 2 * EDIM + t];
        red[t] = acc;
    }
    __syncwarp();
    if (t < EDIM) {
        float inv_n = 1.0f / (float)N_EDGES;
        float mu = red[t] * inv_n;
        float var = red[EDIM + t] * inv_n - mu * mu;
        float sc = rsqrtf(var + BN_EPS) * gamma[t];
        g_scale[t] = sc;
        g_shift[t] = beta[t] - mu * sc;
    }
}

// ---------------- fp16 mma helpers ----------------
__device__ __forceinline__ void mma_f16(float* c, const unsigned* a, unsigned b0, unsigned b1) {
    asm volatile(
        "mma.sync.aligned.m16n8k16.row.col.f32.f16.f16.f32 "
        "{%0,%1,%2,%3}, {%4,%5,%6,%7}, {%8,%9}, {%0,%1,%2,%3};"
        : "+f"(c[0]), "+f"(c[1]), "+f"(c[2]), "+f"(c[3])
        : "r"(a[0]), "r"(a[1]), "r"(a[2]), "r"(a[3]), "r"(b0), "r"(b1));
}

__device__ __forceinline__ void ldsm_x4(unsigned* r, unsigned addr) {
    asm volatile("ldmatrix.sync.aligned.m8n8.x4.shared.b16 {%0,%1,%2,%3}, [%4];"
                 : "=r"(r[0]), "=r"(r[1]), "=r"(r[2]), "=r"(r[3]) : "r"(addr));
}

// ---------------- kernel 4: GEMM1 fp16  P(half) = X @ B[:, 0:1024] ----------------
// Tiles: BM=128, BN=128, K=64. 256 thr, 8 warps (4m x 2n). XOR-swizzled tiles.
// Epilogue staged through smem (pitch 136) for coalesced uint4 stores.
#define EPI_PITCH 136
#define G1_SMEM (128 * EPI_PITCH * 2)   // 34816 B >= tile buffers (32768 B)

__global__ void k_gemm1(const float* __restrict__ x) {
    extern __shared__ char smraw[];
    __half* As = (__half*)smraw;             // [128][64] halves, 16B-chunk swizzle
    __half* Bs = (__half*)smraw + 128 * 64;  // [128 j][64 k] halves, swizzled

    int tid = threadIdx.x;
    int m0 = blockIdx.x * 128;
    int n0 = blockIdx.y * 128;

    // A tile: 128 rows x 8 chunks(16B = 8 halves)
#pragma unroll
    for (int r = 0; r < 4; r++) {
        int id = r * 256 + tid;
        int m = id >> 3, c = id & 7;
        float4 v0 = make_float4(0.f, 0.f, 0.f, 0.f), v1 = v0;
        if (m0 + m < N_NODES) {
            const float* px = &x[(size_t)(m0 + m) * 64 + c * 8];
            v0 = *(const float4*)px;
            v1 = *(const float4*)(px + 4);
        }
        half2 h[4] = {__floats2half2_rn(v0.x, v0.y), __floats2half2_rn(v0.z, v0.w),
                      __floats2half2_rn(v1.x, v1.y), __floats2half2_rn(v1.z, v1.w)};
        *(uint4*)&As[m * 64 + ((c ^ (m & 7)) << 3)] = *(uint4*)h;
    }
    // B tile: rows j = n0..n0+127, 8 chunks each
#pragma unroll
    for (int r = 0; r < 4; r++) {
        int id = r * 256 + tid;
        int j = id >> 3, c = id & 7;
        uint4 v = *(const uint4*)&g_Bh[(size_t)(n0 + j) * 64 + c * 8];
        *(uint4*)&Bs[j * 64 + ((c ^ (j & 7)) << 3)] = v;
    }
    __syncthreads();

    int wid = tid >> 5;
    int lane = tid & 31;
    int warp_m = wid & 3;      // 32 rows
    int warp_n = wid >> 2;     // 64 cols
    int lrow = lane & 15;
    int lsel = lane >> 4;

    unsigned a_base = (unsigned)__cvta_generic_to_shared(As);
    unsigned b_base = (unsigned)__cvta_generic_to_shared(Bs);

    float acc[2][8][4];
#pragma unroll
    for (int mt = 0; mt < 2; mt++)
#pragma unroll
        for (int nt = 0; nt < 8; nt++)
#pragma unroll
            for (int j = 0; j < 4; j++) acc[mt][nt][j] = 0.f;

#pragma unroll
    for (int ks = 0; ks < 4; ks++) {
        int chunk = ks * 2 + lsel;
        unsigned a[2][4];
#pragma unroll
        for (int mt = 0; mt < 2; mt++) {
            int row = warp_m * 32 + mt * 16 + lrow;
            ldsm_x4(a[mt], a_base + (row * 64 + ((chunk ^ (row & 7)) << 3)) * 2);
        }
#pragma unroll
        for (int nt2 = 0; nt2 < 4; nt2++) {
            int row = warp_n * 64 + nt2 * 16 + lrow;
            unsigned b[4];
            ldsm_x4(b, b_base + (row * 64 + ((chunk ^ (row & 7)) << 3)) * 2);
            mma_f16(acc[0][nt2 * 2],     a[0], b[0], b[2]);
            mma_f16(acc[0][nt2 * 2 + 1], a[0], b[1], b[3]);
            mma_f16(acc[1][nt2 * 2],     a[1], b[0], b[2]);
            mma_f16(acc[1][nt2 * 2 + 1], a[1], b[1], b[3]);
        }
    }
    __syncthreads();   // done reading tiles; reuse smem for epilogue staging

    // stage accumulators in smem [128][EPI_PITCH] halves
    __half* Sb = (__half*)smraw;
    int gid = lane >> 2;
    int tig = lane & 3;
#pragma unroll
    for (int mt = 0; mt < 2; mt++) {
#pragma unroll
        for (int nt = 0; nt < 8; nt++) {
            int col = warp_n * 64 + nt * 8 + tig * 2;
            int r0 = warp_m * 32 + mt * 16 + gid;
            *(half2*)&Sb[r0 * EPI_PITCH + col] =
                __floats2half2_rn(acc[mt][nt][0], acc[mt][nt][1]);
            *(half2*)&Sb[(r0 + 8) * EPI_PITCH + col] =
                __floats2half2_rn(acc[mt][nt][2], acc[mt][nt][3]);
        }
    }
    __syncthreads();

    // coalesced store: each thread 16B contiguous, warp covers 2 rows x 256B
#pragma unroll
    for (int r = 0; r < 8; r++) {
        int id = r * 256 + tid;          // 2048 uint4 slots
        int row = id >> 4, c8 = id & 15;
        if (m0 + row < N_NODES) {
            uint4 v = *(uint4*)&Sb[row * EPI_PITCH + c8 * 8];
            *(uint4*)&g_Ph[(size_t)(m0 + row) * PCOLS + n0 + c8 * 8] = v;
        }
    }
}

// ---------------- kernel 5: per-edge message + scatter (fp16 gather) ----------------
__global__ void k_edge(const float* __restrict__ ea, const int* __restrict__ ei) {
    int wg = (blockIdx.x * blockDim.x + threadIdx.x) >> 5;
    int lane = threadIdx.x & 31;
    if (wg >= N_EDGES) return;
    int e = wg;
    int src = ei[e];
    int dst = ei[N_EDGES + e];

    float eb = 0.f;
    if (lane < EDIM) eb = ea[(size_t)e * EDIM + lane] * g_scale[lane] + g_shift[lane];

    const half2* p2 = (const half2*)(g_Ph + (size_t)src * PCOLS);
    float2 acc = __half22float2(p2[384 + lane]);  // bias block at col 768
#pragma unroll
    for (int k = 0; k < EDIM; k++) {
        float c = __shfl_sync(0xffffffffu, eb, k);
        float2 w = __half22float2(p2[k * 32 + lane]);
        acc.x += c * w.x;
        acc.y += c * w.y;
    }
    float* a = g_agg + (size_t)dst * DIM + 2 * lane;
    atomicAdd(a, acc.x);
    atomicAdd(a + 1, acc.y);
    if (lane == 0) atomicAdd(&g_cnt[dst], 1.0f);
}

// ---------------- mma tf32 (gemm2) ----------------
__device__ __forceinline__ void mma_tf32(float* c, const unsigned* a, unsigned b0, unsigned b1) {
    asm volatile(
        "mma.sync.aligned.m16n8k8.row.col.f32.tf32.tf32.f32 "
        "{%0,%1,%2,%3}, {%4,%5,%6,%7}, {%8,%9}, {%0,%1,%2,%3};"
        : "+f"(c[0]), "+f"(c[1]), "+f"(c[2]), "+f"(c[3])
        : "r"(a[0]), "r"(a[1]), "r"(a[2]), "r"(a[3]), "r"(b0), "r"(b1));
}

#define GA_PITCH 68
#define GB_PITCH 132
#define G2_SMEM ((128 * GA_PITCH + 64 * GB_PITCH) * 4)

// ---------------- kernel 6: GEMM2  GI = relu(agg)/cnt @ B[:, 1024:1216] ----------------
__global__ void k_gemm2() {
    extern __shared__ char smraw[];
    float* As = (float*)smraw;
    float* Bs = (float*)smraw + 128 * GA_PITCH;
    const float* Bg = g_B + 1024;
    const int Ncols = 192;

    int tid = threadIdx.x;
    int m0 = blockIdx.x * 128;
    int n0 = blockIdx.y * 128;

#pragma unroll
    for (int r = 0; r < 8; r++) {
        int id = r * 256 + tid;
        int m = id >> 4;
        int k4 = (id & 15) << 2;
        float4 v = make_float4(0.f, 0.f, 0.f, 0.f);
        int node = m0 + m;
        if (node < N_NODES) {
            float inv = 1.0f / fmaxf(g_cnt[node], 1.0f);
            float4 a = *(const float4*)&g_agg[(size_t)node * 64 + k4];
            v.x = fmaxf(a.x, 0.f) * inv;
            v.y = fmaxf(a.y, 0.f) * inv;
            v.z = fmaxf(a.z, 0.f) * inv;
            v.w = fmaxf(a.w, 0.f) * inv;
        }
        v.x = f2tf32(v.x); v.y = f2tf32(v.y); v.z = f2tf32(v.z); v.w = f2tf32(v.w);
        *(float4*)&As[m * GA_PITCH + k4] = v;
    }
#pragma unroll
    for (int r = 0; r < 8; r++) {
        int id = r * 256 + tid;
        int k = id >> 5;
        int n4 = (id & 31) << 2;
        float4 v = make_float4(0.f, 0.f, 0.f, 0.f);
        if (n0 + n4 < Ncols) v = *(const float4*)&Bg[(size_t)k * BCOLS + n0 + n4];
        *(float4*)&Bs[k * GB_PITCH + n4] = v;
    }
    __syncthreads();

    int wid = tid >> 5;
    int lane = tid & 31;
    int gid = lane >> 2;
    int tig = lane & 3;
    int warp_m = wid & 3;
    int warp_n = wid >> 2;

    float acc[2][8][4];
#pragma unroll
    for (int mt = 0; mt < 2; mt++)
#pragma unroll
        for (int nt = 0; nt < 8; nt++)
#pragma unroll
            for (int j = 0; j < 4; j++) acc[mt][nt][j] = 0.f;

#pragma unroll
    for (int ks = 0; ks < 8; ks++) {
        int k0 = ks * 8;
        unsigned a[2][4];
#pragma unroll
        for (int mt = 0; mt < 2; mt++) {
            int rowb = warp_m * 32 + mt * 16;
            a[mt][0] = __float_as_uint(As[(rowb + gid) * GA_PITCH + k0 + tig]);
            a[mt][1] = __float_as_uint(As[(rowb + gid + 8) * GA_PITCH + k0 + tig]);
            a[mt][2] = __float_as_uint(As[(rowb + gid) * GA_PITCH + k0 + tig + 4]);
            a[mt][3] = __float_as_uint(As[(rowb + gid + 8) * GA_PITCH + k0 + tig + 4]);
        }
#pragma unroll
        for (int nt = 0; nt < 8; nt++) {
            int nb = warp_n * 64 + nt * 8 + gid;
            unsigned b0 = __float_as_uint(Bs[(k0 + tig) * GB_PITCH + nb]);
            unsigned b1 = __float_as_uint(Bs[(k0 + tig + 4) * GB_PITCH + nb]);
            mma_tf32(acc[0][nt], a[0], b0, b1);
            mma_tf32(acc[1][nt], a[1], b0, b1);
        }
    }

#pragma unroll
    for (int mt = 0; mt < 2; mt++) {
#pragma unroll
        for (int nt = 0; nt < 8; nt++) {
            int col = n0 + warp_n * 64 + nt * 8 + tig * 2;
            if (col >= Ncols) continue;
            int r0 = m0 + warp_m * 32 + mt * 16 + gid;
            if (r0 < N_NODES)
                *(float2*)&g_GI[(size_t)r0 * 192 + col] = make_float2(acc[mt][nt][0], acc[mt][nt][1]);
            int r1 = r0 + 8;
            if (r1 < N_NODES)
                *(float2*)&g_GI[(size_t)r1 * 192 + col] = make_float2(acc[mt][nt][2], acc[mt][nt][3]);
        }
    }
}

// ---------------- kernel 7: elementwise GRU ----------------
__global__ void k_out(const float* __restrict__ x,
                      const float* __restrict__ bih, const float* __restrict__ bhh,
                      float* __restrict__ out) {
    int idx = blockIdx.x * blockDim.x + threadIdx.x;
    if (idx >= N_NODES * DIM) return;
    int n = idx >> 6;
    int o = idx & 63;

    const float* gi = g_GI + (size_t)n * 192;
    const __half* gh = g_Ph + (size_t)n * PCOLS + 832;

    float ir = gi[o] + bih[o];
    float iz = gi[64 + o] + bih[64 + o];
    float in_ = gi[128 + o] + bih[128 + o];
    float hr = __half2float(gh[o]) + bhh[o];
    float hz = __half2float(gh[64 + o]) + bhh[64 + o];
    float hn = __half2float(gh[128 + o]) + bhh[128 + o];

    float r = 1.0f / (1.0f + __expf(-(ir + hr)));
    float z = 1.0f / (1.0f + __expf(-(iz + hz)));
    float nn = tanhf(in_ + r * hn);
    float xv = x[idx];
    out[idx] = (1.0f - z) * nn + z * xv;
}

// ---------------- host ----------------
extern "C" void kernel_launch(void* const* d_in, const int* in_sizes, int n_in,
                              void* d_out, int out_size) {
    const float* x     = (const float*)d_in[0];
    const int*   ei    = (const int*)d_in[1];
    const float* ea    = (const float*)d_in[2];
    const float* gamma = (const float*)d_in[3];
    const float* beta  = (const float*)d_in[4];
    const float* lw    = (const float*)d_in[5];
    const float* lb    = (const float*)d_in[6];
    const float* wih   = (const float*)d_in[7];
    const float* whh   = (const float*)d_in[8];
    const float* bih   = (const float*)d_in[9];
    const float* bhh   = (const float*)d_in[10];
    float* out = (float*)d_out;

    cudaFuncSetAttribute(k_gemm2, cudaFuncAttributeMaxDynamicSharedMemorySize, G2_SMEM);

    k_pack_zero<<<512, 256>>>(lw, lb, whh, wih);
    k_bn_reduce<<<BN_BLOCKS, 256>>>(ea);
    k_bn_fin<<<1, 32>>>(gamma, beta);

    dim3 g1((N_NODES + 127) / 128, PCOLS / 128);
    k_gemm1<<<g1, 256, G1_SMEM>>>(x);

    k_edge<<<(N_EDGES * 32) / 256, 256>>>(ea, ei);

    dim3 g2((N_NODES + 127) / 128, 2);
    k_gemm2<<<g2, 256, G2_SMEM>>>();

    k_out<<<(N_NODES * DIM + 255) / 256, 256>>>(x, bih, bhh, out);
}